// round 16
// baseline (speedup 1.0000x reference)
#include <cuda_runtime.h>

// selfAttn2d round 16: 3 CTAs/SM retry. P3 made patch-serial to halve its
// register live set (no spills under the 85-reg cap); smem overlay from R15.

__device__ __forceinline__ unsigned int f2tf32(float x) {
    unsigned int r; asm("cvt.rna.tf32.f32 %0, %1;" : "=r"(r) : "f"(x)); return r;
}
__device__ __forceinline__ unsigned int fu(float x) { return __float_as_uint(x); }
__device__ __forceinline__ void mma_tf32(float& d0, float& d1, float& d2, float& d3,
                                         unsigned int a0, unsigned int a1,
                                         unsigned int a2, unsigned int a3,
                                         unsigned int b0, unsigned int b1) {
    asm("mma.sync.aligned.m16n8k8.row.col.f32.tf32.tf32.f32 "
        "{%0,%1,%2,%3},{%4,%5,%6,%7},{%8,%9},{%0,%1,%2,%3};"
        : "+f"(d0), "+f"(d1), "+f"(d2), "+f"(d3)
        : "r"(a0), "r"(a1), "r"(a2), "r"(a3), "r"(b0), "r"(b1));
}

// Prepped tables.
__device__ float g_wa1[12 * 8 * 32 * 4];   // qkv A-frags  [mt][oct][lane][r], tf32
__device__ float g_wa2[4 * 72 * 32 * 4];   // conv A-frags [mt][oct][lane][r], tf32
__device__ float g_wd3[64 * 1024];         // w_deconv B-frags, tf32
__device__ float g_wpt[64 * 64];           // w_proj [j][o]

__global__ void prep_kernel(const float* __restrict__ wq,
                            const float* __restrict__ wk,
                            const float* __restrict__ wv,
                            const float* __restrict__ w_rel,
                            const float* __restrict__ w_deconv,
                            const float* __restrict__ w_proj)
{
    const int i0 = blockIdx.x * blockDim.x + threadIdx.x;
    const int stride = gridDim.x * blockDim.x;
    for (int i = i0; i < 4096; i += stride) {
        int o = i >> 6, c = i & 63;
        g_wpt[(c << 6) | o] = w_proj[i];
    }
    for (int j = i0; j < 12288; j += stride) {
        int r = j & 3, lane = (j >> 2) & 31, oct = (j >> 7) & 7, mt = j >> 10;
        int row = (lane >> 2) + ((r & 1) << 3);
        int k   = oct * 8 + (lane & 3) + ((r >> 1) << 2);
        const float* W = (mt < 4) ? wq : (mt < 8) ? wk : wv;
        g_wa1[j] = __uint_as_float(f2tf32(W[((mt & 3) * 16 + row) * 64 + k]));
    }
    for (int j = i0; j < 36864; j += stride) {
        int r = j & 3, lane = (j >> 2) & 31;
        int mo = j >> 7;
        int mt = mo / 72, oct = mo - mt * 72;
        int u = oct >> 3, jj = oct & 7;
        int ch = mt * 16 + (lane >> 2) + ((r & 1) << 3);
        int c  = jj * 8 + (lane & 3) + ((r >> 1) << 2);
        g_wa2[j] = __uint_as_float(f2tf32(w_rel[ch * 576 + c * 9 + u]));
    }
    for (int j = i0; j < 65536; j += stride) {
        int v    = j & 3;
        int lane = (j >> 2) & 31;
        int rest = j >> 7;
        int npair = rest & 1;
        int koct  = (rest >> 1) & 7;
        int w2    = (rest >> 4) & 7;
        int n     = rest >> 7;
        int noct = npair * 2 + (v >> 1);
        int ch   = koct * 8 + (lane & 3) + (v & 1) * 4;
        int c2   = w2 * 32 + noct * 8 + (lane >> 2);
        int e    = c2 & 15;
        int bd   = c2 >> 4;
        g_wd3[j] = __uint_as_float(f2tf32(w_deconv[ch * 1024 + (n * 16 + e) * 16 + bd]));
    }
}

// Dynamic smem layout (floats), total 19072 (74.5KB):
//   PB(pi)=pi*4736 : per-patch scratch (4736)
//     P0-P2 : PP pair-packed patch [sig(c)][50] = PB+0..3199
//             sp_lin [c][24] = PB+3200..4735  (dead after P1)
//     P2    : partials [8w][16][18] = PB+0..2303 (after inner sync)
//     P2-red: relc_t [ac][68] OVERLAID at PB+3200..4287
//     P4    : abuf PB+2048..3071
//   QT=9472, KT=12032, VS=14592, CS=16896, RL=17024
#define SMEM_FLOATS 19072
#define PBS 4736
#define RCOFF 3200
#define QT 9472
#define KT 12032
#define VS 14592
#define CS 16896
#define RL 17024

__global__ __launch_bounds__(256, 3)
void selfattn2d_kernel(const float* __restrict__ x,
                       const float* __restrict__ w_sf1,
                       const float* __restrict__ b_sf1,
                       const float* __restrict__ w_sf2,
                       const float* __restrict__ b_sf2,
                       const float* __restrict__ b_proj,
                       float* __restrict__ out)
{
    extern __shared__ __align__(16) float S[];
    const int bid = blockIdx.x;
    const int b   = bid >> 9;
    const int t  = threadIdx.x;
    const int lane = t & 31;
    const int w    = t >> 5;

    int oys[2], oxs[2];
#pragma unroll
    for (int pi = 0; pi < 2; pi++) {
        int pb = bid * 2 + pi;
        oys[pi] = (pb >> 5) & 31;
        oxs[pi] = pb & 31;
    }

    // ---------------- Phase 0: load both patches ----------------
    {
        const float* xb = x + b * (64 * 64 * 64);
        for (int idx = t; idx < 4608; idx += 256) {
            int pi = (idx >= 2304) ? 1 : 0;
            int local = idx - pi * 2304;
            int c  = local / 36;
            int r  = local - c * 36;
            int ii = r / 6;
            int jj = r - ii * 6;
            int gy = oys[pi] * 2 + ii - 2;
            int gx = oxs[pi] * 2 + jj - 2;
            float val = 0.f;
            bool inpatch = (ii >= 1 && ii <= 4 && jj >= 1 && jj <= 4);
            if (inpatch && gy >= 0 && gy < 64 && gx >= 0 && gx < 64)
                val = xb[c * 4096 + gy * 64 + gx];
            val = __uint_as_float(f2tf32(val));
            const int sg = (c & 15) * 4 + (c >> 4);
            float* PP = S + pi * PBS + sg * 50;
            if (ii <= 3) PP[2 * r] = val;
            if (ii >= 2) PP[2 * (r - 12) + 1] = val;
            if (inpatch)
                S[pi * PBS + 3200 + c * 24 + (ii - 1) * 4 + (jj - 1)] = val;
        }
    }
    __syncthreads();

    // ---------------- Phase 1: q/k/v on tensor cores (balanced tasks) ----------------
    {
        const int base0 = (lane & 3) * 24 + (lane >> 2);
        const int g = lane >> 2, tg = lane & 3;
#pragma unroll
        for (int it = 0; it < 3; it++) {
            const int task = it * 8 + w;
            const int mt = task >> 1;
            const int pi = task & 1;
            float acc[8];
#pragma unroll
            for (int p = 0; p < 8; p++) acc[p] = 0.f;
            const float4* wa = ((const float4*)g_wa1) + mt * 256 + lane;
            const float* bp0 = S + pi * PBS + 3200 + base0;
#pragma unroll
            for (int oct = 0; oct < 8; oct++) {
                float4 A4 = wa[oct * 32];
                const float* bp = bp0 + oct * 192;
                float b0 = bp[0], b1 = bp[96];
                float c0 = bp[8], c1 = bp[104];
                mma_tf32(acc[0], acc[1], acc[2], acc[3],
                         fu(A4.x), fu(A4.y), fu(A4.z), fu(A4.w), fu(b0), fu(b1));
                mma_tf32(acc[4], acc[5], acc[6], acc[7],
                         fu(A4.x), fu(A4.y), fu(A4.z), fu(A4.w), fu(c0), fu(c1));
            }
            if (mt < 8) {
                const float sc = (mt < 4) ? 0.25f : 1.0f;
                const int n2 = mt & 3;
                float* bp2 = S + ((mt < 4) ? QT : KT) + n2 * 320 + pi * 1280;
                bp2[(2 * tg) * 20 + g]         = acc[0] * sc;
                bp2[(2 * tg + 1) * 20 + g]     = acc[1] * sc;
                bp2[(2 * tg) * 20 + g + 8]     = acc[2] * sc;
                bp2[(2 * tg + 1) * 20 + g + 8] = acc[3] * sc;
                bp2[(2 * tg + 8) * 20 + g]         = acc[4] * sc;
                bp2[(2 * tg + 9) * 20 + g]         = acc[5] * sc;
                bp2[(2 * tg + 8) * 20 + g + 8]     = acc[6] * sc;
                bp2[(2 * tg + 9) * 20 + g + 8]     = acc[7] * sc;
            } else {
                const int n2 = mt - 8;
                const int col = 2 * tg;
                float* dst = S + VS + pi * 1152 + n2 * 288;
                *(float2*)(dst + g * 18 + col)           = make_float2(acc[0], acc[1]);
                *(float2*)(dst + (g + 8) * 18 + col)     = make_float2(acc[2], acc[3]);
                *(float2*)(dst + g * 18 + col + 8)       = make_float2(acc[4], acc[5]);
                *(float2*)(dst + (g + 8) * 18 + col + 8) = make_float2(acc[6], acc[7]);
            }
        }
    }

    // ---------------- Phase 2: rel_c conv on tensor cores (pair-packed loads) ----------------
    {
        const int mt = w & 3, halfk = w >> 2;
        float acc[2][8];
#pragma unroll
        for (int pi = 0; pi < 2; pi++)
#pragma unroll
            for (int p = 0; p < 8; p++) acc[pi][p] = 0.f;
        const float4* wa = ((const float4*)g_wa2) + mt * 2304 + lane;
        const int q50 = (lane & 3) * 200;
        const int ac = lane >> 2;
        const int Pa = (ac >> 2) * 6 + (ac & 3);
#pragma unroll
        for (int u = 0; u < 9; u++) {
            bool mine = (halfk == 0) ? (u < 5) : (u >= 5);
            if (mine) {
                const int P = Pa + (u / 3) * 6 + (u % 3);
#pragma unroll
                for (int j = 0; j < 8; j++) {
                    float4 A4 = wa[(u * 8 + j) * 32];
                    const int boff = q50 + (j & 1) * 1600 + (j >> 1) * 50 + 2 * P;
#pragma unroll
                    for (int pi = 0; pi < 2; pi++) {
                        const float* sp = S + pi * PBS + boff;
                        float2 v0 = *(const float2*)sp;
                        float2 v1 = *(const float2*)(sp + 800);
                        mma_tf32(acc[pi][0], acc[pi][1], acc[pi][2], acc[pi][3],
                                 fu(A4.x), fu(A4.y), fu(A4.z), fu(A4.w), fu(v0.x), fu(v1.x));
                        mma_tf32(acc[pi][4], acc[pi][5], acc[pi][6], acc[pi][7],
                                 fu(A4.x), fu(A4.y), fu(A4.z), fu(A4.w), fu(v0.y), fu(v1.y));
                    }
                }
            }
        }
        __syncthreads();     // all patch (and sp_lin) reads complete
        const int row = lane >> 2, col = 2 * (lane & 3);
#pragma unroll
        for (int pi = 0; pi < 2; pi++) {
            float* rp = S + pi * PBS + w * 288;
            *(float2*)(rp + row * 18 + col)           = make_float2(acc[pi][0], acc[pi][1]);
            *(float2*)(rp + (row + 8) * 18 + col)     = make_float2(acc[pi][2], acc[pi][3]);
            *(float2*)(rp + row * 18 + col + 8)       = make_float2(acc[pi][4], acc[pi][5]);
            *(float2*)(rp + (row + 8) * 18 + col + 8) = make_float2(acc[pi][6], acc[pi][7]);
        }
    }
    __syncthreads();
    // reduce u-halves into relc_t[pi][ac][ch] (overlaid on dead sp_lin), tf32
    {
#pragma unroll
        for (int it = 0; it < 2; it++) {
            int task = t + it * 256;
            int pi = task >> 8;
            int rem = task & 255;
            int ac2 = rem >> 4;
            int chq = rem & 15;
            int mt2 = chq >> 2;
            const float* pa = S + pi * PBS + mt2 * 288 + ((chq & 3) * 4) * 18 + ac2;
            const float* pb2 = pa + 4 * 288;
            float4 v4;
            v4.x = __uint_as_float(f2tf32(pa[0]  + pb2[0]));
            v4.y = __uint_as_float(f2tf32(pa[18] + pb2[18]));
            v4.z = __uint_as_float(f2tf32(pa[36] + pb2[36]));
            v4.w = __uint_as_float(f2tf32(pa[54] + pb2[54]));
            *(float4*)(S + pi * PBS + RCOFF + ac2 * 68 + chq * 4) = v4;
        }
    }
    __syncthreads();

    // ---------------- Phase 3: GEMM + in-register e-contraction (patch-serial) ----------------
    // warp w owns cols c2 in [w*32, w*32+32) => bd in {2w, 2w+1}, all 16 e's.
    {
        const int g = lane >> 2, tg = lane & 3;
#pragma unroll
        for (int pi = 0; pi < 2; pi++) {
            const float* rcb = S + pi * PBS + RCOFF;
#pragma unroll
            for (int n = 0; n < 4; n++) {
                float acc[4][4];
#pragma unroll
                for (int no = 0; no < 4; no++)
#pragma unroll
                    for (int r = 0; r < 4; r++) acc[no][r] = 0.f;
                const float4* wd4 = ((const float4*)g_wd3) + ((n * 8 + w) * 8) * 2 * 32 + lane;
#pragma unroll
                for (int koct = 0; koct < 8; koct++) {
                    const float* rc = rcb + koct * 8 + tg;
                    unsigned int a0 = fu(rc[g * 68]);
                    unsigned int a1 = fu(rc[(g + 8) * 68]);
                    unsigned int a2 = fu(rc[g * 68 + 4]);
                    unsigned int a3 = fu(rc[(g + 8) * 68 + 4]);
#pragma unroll
                    for (int npair = 0; npair < 2; npair++) {
                        float4 B4 = wd4[(koct * 2 + npair) * 32];
                        mma_tf32(acc[npair * 2][0], acc[npair * 2][1],
                                 acc[npair * 2][2], acc[npair * 2][3],
                                 a0, a1, a2, a3, fu(B4.x), fu(B4.y));
                        mma_tf32(acc[npair * 2 + 1][0], acc[npair * 2 + 1][1],
                                 acc[npair * 2 + 1][2], acc[npair * 2 + 1][3],
                                 a0, a1, a2, a3, fu(B4.z), fu(B4.w));
                    }
                }
                // e-contraction: lane holds e = {2tg,2tg+1,8+2tg,8+2tg+1}
                const float* qt = S + QT + pi * 1280 + n * 320;
                float2 qg0 = *(const float2*)(qt + g * 20 + 2 * tg);
                float2 qg1 = *(const float2*)(qt + g * 20 + 8 + 2 * tg);
                float2 qh0 = *(const float2*)(qt + (g + 8) * 20 + 2 * tg);
                float2 qh1 = *(const float2*)(qt + (g + 8) * 20 + 8 + 2 * tg);
                float r_[4];
                r_[0] = qg0.x * acc[0][0] + qg0.y * acc[0][1]
                      + qg1.x * acc[1][0] + qg1.y * acc[1][1];
                r_[1] = qg0.x * acc[2][0] + qg0.y * acc[2][1]
                      + qg1.x * acc[3][0] + qg1.y * acc[3][1];
                r_[2] = qh0.x * acc[0][2] + qh0.y * acc[0][3]
                      + qh1.x * acc[1][2] + qh1.y * acc[1][3];
                r_[3] = qh0.x * acc[2][2] + qh0.y * acc[2][3]
                      + qh1.x * acc[3][2] + qh1.y * acc[3][3];
#pragma unroll
                for (int i = 0; i < 4; i++) {
                    r_[i] += __shfl_xor_sync(0xffffffffu, r_[i], 1);
                    r_[i] += __shfl_xor_sync(0xffffffffu, r_[i], 2);
                }
                if (tg == 0) {
                    float* rl = S + RL + pi * 1024 + n * 256;
                    rl[g * 16 + 2 * w]           = r_[0];
                    rl[g * 16 + 2 * w + 1]       = r_[1];
                    rl[(g + 8) * 16 + 2 * w]     = r_[2];
                    rl[(g + 8) * 16 + 2 * w + 1] = r_[3];
                }
            }
        }
    }
    __syncthreads();

    // ---------------- Phase 4: MLP + softmax + attention (shfl partner exchange) ----------------
    {
        const int pi = t >> 7, tl = t & 127;
        const int n = tl >> 5, p = (tl >> 1) & 15, hf = tl & 1;
        const float4* q4 = (const float4*)(S + QT + pi * 1280 + n * 320 + p * 20);
        const float4* k4 = (const float4*)(S + KT + pi * 1280 + n * 320 + p * 20);
        float4 qv[4], kv[4];
#pragma unroll
        for (int i4 = 0; i4 < 4; i4++) { qv[i4] = q4[i4]; kv[i4] = k4[i4]; }
        float h1v[8];
#pragma unroll
        for (int hh = 0; hh < 8; hh++) {
            int h = hf * 8 + hh;
            float s = b_sf1[h];
            const float4* w14 = (const float4*)(w_sf1 + h * 32);
#pragma unroll
            for (int i4 = 0; i4 < 4; i4++) {
                float4 wq4 = w14[i4];
                s += wq4.x * ((const float*)&qv[i4])[0] + wq4.y * ((const float*)&qv[i4])[1]
                   + wq4.z * ((const float*)&qv[i4])[2] + wq4.w * ((const float*)&qv[i4])[3];
            }
#pragma unroll
            for (int i4 = 0; i4 < 4; i4++) {
                float4 wk4 = w14[4 + i4];
                s += wk4.x * ((const float*)&kv[i4])[0] + wk4.y * ((const float*)&kv[i4])[1]
                   + wk4.z * ((const float*)&kv[i4])[2] + wk4.w * ((const float*)&kv[i4])[3];
            }
            h1v[hh] = tanhf(s);
        }
        float hv[16];
#pragma unroll
        for (int i = 0; i < 8; i++) {
            float other = __shfl_xor_sync(0xffffffffu, h1v[i], 1);
            if (hf == 0) { hv[i] = h1v[i]; hv[8 + i] = other; }
            else         { hv[i] = other;  hv[8 + i] = h1v[i]; }
        }
        const float* rp = S + RL + pi * 1024 + n * 256 + p * 16;
        float lg[8];
        float mx = -1e30f;
#pragma unroll
        for (int mm = 0; mm < 8; mm++) {
            int m = hf * 8 + mm;
            float s = b_sf2[m];
            const float4* w24 = (const float4*)(w_sf2 + m * 16);
#pragma unroll
            for (int i4 = 0; i4 < 4; i4++) {
                float4 w4 = w24[i4];
                s += w4.x * hv[4 * i4] + w4.y * hv[4 * i4 + 1]
                   + w4.z * hv[4 * i4 + 2] + w4.w * hv[4 * i4 + 3];
            }
            s += rp[m];
            lg[mm] = s;
            mx = fmaxf(mx, s);
        }
        mx = fmaxf(mx, __shfl_xor_sync(0xffffffffu, mx, 1));
        float den = 0.f;
#pragma unroll
        for (int mm = 0; mm < 8; mm++) { lg[mm] = __expf(lg[mm] - mx); den += lg[mm]; }
        den += __shfl_xor_sync(0xffffffffu, den, 1);
        const float inv = 1.0f / den;
        float wv_[16];
#pragma unroll
        for (int i = 0; i < 8; i++) {
            float mine  = lg[i] * inv;
            float other = __shfl_xor_sync(0xffffffffu, mine, 1);
            if (hf == 0) { wv_[i] = mine;  wv_[8 + i] = other; }
            else         { wv_[i] = other; wv_[8 + i] = mine;  }
        }
        float av[8];
        const float* vbase = S + VS + pi * 1152 + n * 288;
#pragma unroll
        for (int dd = 0; dd < 8; dd++) {
            int dv = hf * 8 + dd;
            const float2* vr = (const float2*)(vbase + dv * 18);
            float a = 0.f;
#pragma unroll
            for (int m2 = 0; m2 < 8; m2++) {
                float2 vv = vr[m2];
                a += wv_[2 * m2] * vv.x + wv_[2 * m2 + 1] * vv.y;
            }
            av[dd] = a;
        }
        float* ab = S + pi * PBS + 2048 + (n * 16 + p) * 16 + hf * 8;
        *(float4*)ab       = make_float4(av[0], av[1], av[2], av[3]);
        *(float4*)(ab + 4) = make_float4(av[4], av[5], av[6], av[7]);
    }
    __syncthreads();
    if (t < 128) {
        const int pi = t >> 6, tl = t & 63;
        const int plo = tl >> 4;
        const int dv  = tl & 15;
        const float* ab = S + pi * PBS + 2048;
        float s = 0.f;
#pragma unroll
        for (int n2 = 0; n2 < 4; n2++)
#pragma unroll
            for (int ph = 0; ph < 4; ph++)
                s += ab[(n2 * 16 + ph * 4 + plo) * 16 + dv];
        S[CS + pi * 64 + tl] = s;
    }
    __syncthreads();

    // ---------------- Phase 5: projection + sum ----------------
    if (t < 128) {
        const int pi = t >> 6, o = t & 63;
        const float* cs = S + CS + pi * 64;
        float acc = 16.0f * b_proj[o];
#pragma unroll 8
        for (int j = 0; j < 64; j++) acc += cs[j] * g_wpt[(j << 6) | o];
        out[b * 65536 + o * 1024 + oys[pi] * 32 + oxs[pi]] = acc;
    }
}

extern "C" void kernel_launch(void* const* d_in, const int* in_sizes, int n_in,
                              void* d_out, int out_size)
{
    (void)in_sizes; (void)n_in; (void)out_size;
    cudaFuncSetAttribute(selfattn2d_kernel,
                         cudaFuncAttributeMaxDynamicSharedMemorySize,
                         SMEM_FLOATS * sizeof(float));
    prep_kernel<<<64, 256>>>(
        (const float*)d_in[1],  // wq
        (const float*)d_in[2],  // wk
        (const float*)d_in[3],  // wv
        (const float*)d_in[4],  // w_rel
        (const float*)d_in[5],  // w_deconv
        (const float*)d_in[10]);// w_proj
    selfattn2d_kernel<<<2048, 256, SMEM_FLOATS * sizeof(float)>>>(
        (const float*)d_in[0],  // x
        (const float*)d_in[6],  // w_sf1
        (const float*)d_in[7],  // b_sf1
        (const float*)d_in[8],  // w_sf2
        (const float*)d_in[9],  // b_sf2
        (const float*)d_in[11], // b_proj
        (float*)d_out);
}

// round 17
// speedup vs baseline: 2.2393x; 2.2393x over previous
#include <cuda_runtime.h>

// selfAttn2d round 17: revert to the proven 2-CTA/SM configuration (R14),
// keeping the harmless smem overlay; float2 rl stores in P3.

__device__ __forceinline__ unsigned int f2tf32(float x) {
    unsigned int r; asm("cvt.rna.tf32.f32 %0, %1;" : "=r"(r) : "f"(x)); return r;
}
__device__ __forceinline__ unsigned int fu(float x) { return __float_as_uint(x); }
__device__ __forceinline__ void mma_tf32(float& d0, float& d1, float& d2, float& d3,
                                         unsigned int a0, unsigned int a1,
                                         unsigned int a2, unsigned int a3,
                                         unsigned int b0, unsigned int b1) {
    asm("mma.sync.aligned.m16n8k8.row.col.f32.tf32.tf32.f32 "
        "{%0,%1,%2,%3},{%4,%5,%6,%7},{%8,%9},{%0,%1,%2,%3};"
        : "+f"(d0), "+f"(d1), "+f"(d2), "+f"(d3)
        : "r"(a0), "r"(a1), "r"(a2), "r"(a3), "r"(b0), "r"(b1));
}

// Prepped tables.
__device__ float g_wa1[12 * 8 * 32 * 4];   // qkv A-frags  [mt][oct][lane][r], tf32
__device__ float g_wa2[4 * 72 * 32 * 4];   // conv A-frags [mt][oct][lane][r], tf32
__device__ float g_wd3[64 * 1024];         // w_deconv B-frags, tf32
__device__ float g_wpt[64 * 64];           // w_proj [j][o]

__global__ void prep_kernel(const float* __restrict__ wq,
                            const float* __restrict__ wk,
                            const float* __restrict__ wv,
                            const float* __restrict__ w_rel,
                            const float* __restrict__ w_deconv,
                            const float* __restrict__ w_proj)
{
    const int i0 = blockIdx.x * blockDim.x + threadIdx.x;
    const int stride = gridDim.x * blockDim.x;
    for (int i = i0; i < 4096; i += stride) {
        int o = i >> 6, c = i & 63;
        g_wpt[(c << 6) | o] = w_proj[i];
    }
    for (int j = i0; j < 12288; j += stride) {
        int r = j & 3, lane = (j >> 2) & 31, oct = (j >> 7) & 7, mt = j >> 10;
        int row = (lane >> 2) + ((r & 1) << 3);
        int k   = oct * 8 + (lane & 3) + ((r >> 1) << 2);
        const float* W = (mt < 4) ? wq : (mt < 8) ? wk : wv;
        g_wa1[j] = __uint_as_float(f2tf32(W[((mt & 3) * 16 + row) * 64 + k]));
    }
    for (int j = i0; j < 36864; j += stride) {
        int r = j & 3, lane = (j >> 2) & 31;
        int mo = j >> 7;
        int mt = mo / 72, oct = mo - mt * 72;
        int u = oct >> 3, jj = oct & 7;
        int ch = mt * 16 + (lane >> 2) + ((r & 1) << 3);
        int c  = jj * 8 + (lane & 3) + ((r >> 1) << 2);
        g_wa2[j] = __uint_as_float(f2tf32(w_rel[ch * 576 + c * 9 + u]));
    }
    for (int j = i0; j < 65536; j += stride) {
        int v    = j & 3;
        int lane = (j >> 2) & 31;
        int rest = j >> 7;
        int npair = rest & 1;
        int koct  = (rest >> 1) & 7;
        int w2    = (rest >> 4) & 7;
        int n     = rest >> 7;
        int noct = npair * 2 + (v >> 1);
        int ch   = koct * 8 + (lane & 3) + (v & 1) * 4;
        int c2   = w2 * 32 + noct * 8 + (lane >> 2);
        int e    = c2 & 15;
        int bd   = c2 >> 4;
        g_wd3[j] = __uint_as_float(f2tf32(w_deconv[ch * 1024 + (n * 16 + e) * 16 + bd]));
    }
}

// Dynamic smem layout (floats), total 19072 (74.5KB):
//   PB(pi)=pi*4736 : per-patch scratch (4736)
//     P0-P2 : PP pair-packed patch [sig(c)][50] = PB+0..3199
//             sp_lin [c][24] = PB+3200..4735  (dead after P1)
//     P2    : partials [8w][16][18] = PB+0..2303 (after inner sync)
//     P2-red: relc_t [ac][68] OVERLAID at PB+3200..4287
//     P4    : abuf PB+2048..3071
//   QT=9472, KT=12032, VS=14592, CS=16896, RL=17024
#define SMEM_FLOATS 19072
#define PBS 4736
#define RCOFF 3200
#define QT 9472
#define KT 12032
#define VS 14592
#define CS 16896
#define RL 17024

__global__ __launch_bounds__(256, 2)
void selfattn2d_kernel(const float* __restrict__ x,
                       const float* __restrict__ w_sf1,
                       const float* __restrict__ b_sf1,
                       const float* __restrict__ w_sf2,
                       const float* __restrict__ b_sf2,
                       const float* __restrict__ b_proj,
                       float* __restrict__ out)
{
    extern __shared__ __align__(16) float S[];
    const int bid = blockIdx.x;
    const int b   = bid >> 9;
    const int t  = threadIdx.x;
    const int lane = t & 31;
    const int w    = t >> 5;

    int oys[2], oxs[2];
#pragma unroll
    for (int pi = 0; pi < 2; pi++) {
        int pb = bid * 2 + pi;
        oys[pi] = (pb >> 5) & 31;
        oxs[pi] = pb & 31;
    }

    // ---------------- Phase 0: load both patches ----------------
    {
        const float* xb = x + b * (64 * 64 * 64);
        for (int idx = t; idx < 4608; idx += 256) {
            int pi = (idx >= 2304) ? 1 : 0;
            int local = idx - pi * 2304;
            int c  = local / 36;
            int r  = local - c * 36;
            int ii = r / 6;
            int jj = r - ii * 6;
            int gy = oys[pi] * 2 + ii - 2;
            int gx = oxs[pi] * 2 + jj - 2;
            float val = 0.f;
            bool inpatch = (ii >= 1 && ii <= 4 && jj >= 1 && jj <= 4);
            if (inpatch && gy >= 0 && gy < 64 && gx >= 0 && gx < 64)
                val = xb[c * 4096 + gy * 64 + gx];
            val = __uint_as_float(f2tf32(val));
            const int sg = (c & 15) * 4 + (c >> 4);
            float* PP = S + pi * PBS + sg * 50;
            if (ii <= 3) PP[2 * r] = val;
            if (ii >= 2) PP[2 * (r - 12) + 1] = val;
            if (inpatch)
                S[pi * PBS + 3200 + c * 24 + (ii - 1) * 4 + (jj - 1)] = val;
        }
    }
    __syncthreads();

    // ---------------- Phase 1: q/k/v on tensor cores (balanced tasks) ----------------
    // 24 tasks = (mt 0..11) x (pi 0..1); warp w runs tasks {w, w+8, w+16}: 3 each.
    {
        const int base0 = (lane & 3) * 24 + (lane >> 2);
        const int g = lane >> 2, tg = lane & 3;
#pragma unroll
        for (int it = 0; it < 3; it++) {
            const int task = it * 8 + w;
            const int mt = task >> 1;
            const int pi = task & 1;
            float acc[8];
#pragma unroll
            for (int p = 0; p < 8; p++) acc[p] = 0.f;
            const float4* wa = ((const float4*)g_wa1) + mt * 256 + lane;
            const float* bp0 = S + pi * PBS + 3200 + base0;
#pragma unroll
            for (int oct = 0; oct < 8; oct++) {
                float4 A4 = wa[oct * 32];
                const float* bp = bp0 + oct * 192;
                float b0 = bp[0], b1 = bp[96];
                float c0 = bp[8], c1 = bp[104];
                mma_tf32(acc[0], acc[1], acc[2], acc[3],
                         fu(A4.x), fu(A4.y), fu(A4.z), fu(A4.w), fu(b0), fu(b1));
                mma_tf32(acc[4], acc[5], acc[6], acc[7],
                         fu(A4.x), fu(A4.y), fu(A4.z), fu(A4.w), fu(c0), fu(c1));
            }
            if (mt < 8) {
                const float sc = (mt < 4) ? 0.25f : 1.0f;
                const int n2 = mt & 3;
                float* bp2 = S + ((mt < 4) ? QT : KT) + n2 * 320 + pi * 1280;
                bp2[(2 * tg) * 20 + g]         = acc[0] * sc;
                bp2[(2 * tg + 1) * 20 + g]     = acc[1] * sc;
                bp2[(2 * tg) * 20 + g + 8]     = acc[2] * sc;
                bp2[(2 * tg + 1) * 20 + g + 8] = acc[3] * sc;
                bp2[(2 * tg + 8) * 20 + g]         = acc[4] * sc;
                bp2[(2 * tg + 9) * 20 + g]         = acc[5] * sc;
                bp2[(2 * tg + 8) * 20 + g + 8]     = acc[6] * sc;
                bp2[(2 * tg + 9) * 20 + g + 8]     = acc[7] * sc;
            } else {
                const int n2 = mt - 8;
                const int col = 2 * tg;
                float* dst = S + VS + pi * 1152 + n2 * 288;
                *(float2*)(dst + g * 18 + col)           = make_float2(acc[0], acc[1]);
                *(float2*)(dst + (g + 8) * 18 + col)     = make_float2(acc[2], acc[3]);
                *(float2*)(dst + g * 18 + col + 8)       = make_float2(acc[4], acc[5]);
                *(float2*)(dst + (g + 8) * 18 + col + 8) = make_float2(acc[6], acc[7]);
            }
        }
    }

    // ---------------- Phase 2: rel_c conv on tensor cores (pair-packed loads) ----------------
    {
        const int mt = w & 3, halfk = w >> 2;
        float acc[2][8];
#pragma unroll
        for (int pi = 0; pi < 2; pi++)
#pragma unroll
            for (int p = 0; p < 8; p++) acc[pi][p] = 0.f;
        const float4* wa = ((const float4*)g_wa2) + mt * 2304 + lane;
        const int q50 = (lane & 3) * 200;
        const int ac = lane >> 2;
        const int Pa = (ac >> 2) * 6 + (ac & 3);
#pragma unroll
        for (int u = 0; u < 9; u++) {
            bool mine = (halfk == 0) ? (u < 5) : (u >= 5);
            if (mine) {
                const int P = Pa + (u / 3) * 6 + (u % 3);
#pragma unroll
                for (int j = 0; j < 8; j++) {
                    float4 A4 = wa[(u * 8 + j) * 32];
                    const int boff = q50 + (j & 1) * 1600 + (j >> 1) * 50 + 2 * P;
#pragma unroll
                    for (int pi = 0; pi < 2; pi++) {
                        const float* sp = S + pi * PBS + boff;
                        float2 v0 = *(const float2*)sp;
                        float2 v1 = *(const float2*)(sp + 800);
                        mma_tf32(acc[pi][0], acc[pi][1], acc[pi][2], acc[pi][3],
                                 fu(A4.x), fu(A4.y), fu(A4.z), fu(A4.w), fu(v0.x), fu(v1.x));
                        mma_tf32(acc[pi][4], acc[pi][5], acc[pi][6], acc[pi][7],
                                 fu(A4.x), fu(A4.y), fu(A4.z), fu(A4.w), fu(v0.y), fu(v1.y));
                    }
                }
            }
        }
        __syncthreads();     // all patch (and sp_lin) reads complete
        const int row = lane >> 2, col = 2 * (lane & 3);
#pragma unroll
        for (int pi = 0; pi < 2; pi++) {
            float* rp = S + pi * PBS + w * 288;
            *(float2*)(rp + row * 18 + col)           = make_float2(acc[pi][0], acc[pi][1]);
            *(float2*)(rp + (row + 8) * 18 + col)     = make_float2(acc[pi][2], acc[pi][3]);
            *(float2*)(rp + row * 18 + col + 8)       = make_float2(acc[pi][4], acc[pi][5]);
            *(float2*)(rp + (row + 8) * 18 + col + 8) = make_float2(acc[pi][6], acc[pi][7]);
        }
    }
    __syncthreads();
    // reduce u-halves into relc_t[pi][ac][ch] (overlaid on dead sp_lin), tf32
    {
#pragma unroll
        for (int it = 0; it < 2; it++) {
            int task = t + it * 256;
            int pi = task >> 8;
            int rem = task & 255;
            int ac2 = rem >> 4;
            int chq = rem & 15;
            int mt2 = chq >> 2;
            const float* pa = S + pi * PBS + mt2 * 288 + ((chq & 3) * 4) * 18 + ac2;
            const float* pb2 = pa + 4 * 288;
            float4 v4;
            v4.x = __uint_as_float(f2tf32(pa[0]  + pb2[0]));
            v4.y = __uint_as_float(f2tf32(pa[18] + pb2[18]));
            v4.z = __uint_as_float(f2tf32(pa[36] + pb2[36]));
            v4.w = __uint_as_float(f2tf32(pa[54] + pb2[54]));
            *(float4*)(S + pi * PBS + RCOFF + ac2 * 68 + chq * 4) = v4;
        }
    }
    __syncthreads();

    // ---------------- Phase 3: GEMM + in-register e-contraction (per n) ----------------
    // warp w owns cols c2 in [w*32, w*32+32) => bd in {2w, 2w+1}, all 16 e's.
    {
        const int g = lane >> 2, tg = lane & 3;
#pragma unroll
        for (int n = 0; n < 4; n++) {
            float acc[2][4][4];
#pragma unroll
            for (int pi = 0; pi < 2; pi++)
#pragma unroll
                for (int no = 0; no < 4; no++)
#pragma unroll
                    for (int r = 0; r < 4; r++) acc[pi][no][r] = 0.f;
            const float4* wd4 = ((const float4*)g_wd3) + ((n * 8 + w) * 8) * 2 * 32 + lane;
#pragma unroll
            for (int koct = 0; koct < 8; koct++) {
                unsigned int a[2][4];
#pragma unroll
                for (int pi = 0; pi < 2; pi++) {
                    const float* rc = S + pi * PBS + RCOFF + koct * 8 + tg;
                    a[pi][0] = fu(rc[g * 68]);
                    a[pi][1] = fu(rc[(g + 8) * 68]);
                    a[pi][2] = fu(rc[g * 68 + 4]);
                    a[pi][3] = fu(rc[(g + 8) * 68 + 4]);
                }
#pragma unroll
                for (int npair = 0; npair < 2; npair++) {
                    float4 B4 = wd4[(koct * 2 + npair) * 32];
#pragma unroll
                    for (int pi = 0; pi < 2; pi++) {
                        mma_tf32(acc[pi][npair * 2][0], acc[pi][npair * 2][1],
                                 acc[pi][npair * 2][2], acc[pi][npair * 2][3],
                                 a[pi][0], a[pi][1], a[pi][2], a[pi][3],
                                 fu(B4.x), fu(B4.y));
                        mma_tf32(acc[pi][npair * 2 + 1][0], acc[pi][npair * 2 + 1][1],
                                 acc[pi][npair * 2 + 1][2], acc[pi][npair * 2 + 1][3],
                                 a[pi][0], a[pi][1], a[pi][2], a[pi][3],
                                 fu(B4.z), fu(B4.w));
                    }
                }
            }
#pragma unroll
            for (int pi = 0; pi < 2; pi++) {
                const float* qt = S + QT + pi * 1280 + n * 320;
                float2 qg0 = *(const float2*)(qt + g * 20 + 2 * tg);
                float2 qg1 = *(const float2*)(qt + g * 20 + 8 + 2 * tg);
                float2 qh0 = *(const float2*)(qt + (g + 8) * 20 + 2 * tg);
                float2 qh1 = *(const float2*)(qt + (g + 8) * 20 + 8 + 2 * tg);
                float r_[4];
                r_[0] = qg0.x * acc[pi][0][0] + qg0.y * acc[pi][0][1]
                      + qg1.x * acc[pi][1][0] + qg1.y * acc[pi][1][1];
                r_[1] = qg0.x * acc[pi][2][0] + qg0.y * acc[pi][2][1]
                      + qg1.x * acc[pi][3][0] + qg1.y * acc[pi][3][1];
                r_[2] = qh0.x * acc[pi][0][2] + qh0.y * acc[pi][0][3]
                      + qh1.x * acc[pi][1][2] + qh1.y * acc[pi][1][3];
                r_[3] = qh0.x * acc[pi][2][2] + qh0.y * acc[pi][2][3]
                      + qh1.x * acc[pi][3][2] + qh1.y * acc[pi][3][3];
#pragma unroll
                for (int i = 0; i < 4; i++) {
                    r_[i] += __shfl_xor_sync(0xffffffffu, r_[i], 1);
                    r_[i] += __shfl_xor_sync(0xffffffffu, r_[i], 2);
                }
                if (tg == 0) {
                    float* rl = S + RL + pi * 1024 + n * 256;
                    *(float2*)(rl + g * 16 + 2 * w)       = make_float2(r_[0], r_[1]);
                    *(float2*)(rl + (g + 8) * 16 + 2 * w) = make_float2(r_[2], r_[3]);
                }
            }
        }
    }
    __syncthreads();

    // ---------------- Phase 4: MLP + softmax + attention (shfl partner exchange) ----------------
    {
        const int pi = t >> 7, tl = t & 127;
        const int n = tl >> 5, p = (tl >> 1) & 15, hf = tl & 1;
        const float4* q4 = (const float4*)(S + QT + pi * 1280 + n * 320 + p * 20);
        const float4* k4 = (const float4*)(S + KT + pi * 1280 + n * 320 + p * 20);
        float4 qv[4], kv[4];
#pragma unroll
        for (int i4 = 0; i4 < 4; i4++) { qv[i4] = q4[i4]; kv[i4] = k4[i4]; }
        float h1v[8];
#pragma unroll
        for (int hh = 0; hh < 8; hh++) {
            int h = hf * 8 + hh;
            float s = b_sf1[h];
            const float4* w14 = (const float4*)(w_sf1 + h * 32);
#pragma unroll
            for (int i4 = 0; i4 < 4; i4++) {
                float4 wq4 = w14[i4];
                s += wq4.x * ((const float*)&qv[i4])[0] + wq4.y * ((const float*)&qv[i4])[1]
                   + wq4.z * ((const float*)&qv[i4])[2] + wq4.w * ((const float*)&qv[i4])[3];
            }
#pragma unroll
            for (int i4 = 0; i4 < 4; i4++) {
                float4 wk4 = w14[4 + i4];
                s += wk4.x * ((const float*)&kv[i4])[0] + wk4.y * ((const float*)&kv[i4])[1]
                   + wk4.z * ((const float*)&kv[i4])[2] + wk4.w * ((const float*)&kv[i4])[3];
            }
            h1v[hh] = tanhf(s);
        }
        float hv[16];
#pragma unroll
        for (int i = 0; i < 8; i++) {
            float other = __shfl_xor_sync(0xffffffffu, h1v[i], 1);
            if (hf == 0) { hv[i] = h1v[i]; hv[8 + i] = other; }
            else         { hv[i] = other;  hv[8 + i] = h1v[i]; }
        }
        const float* rp = S + RL + pi * 1024 + n * 256 + p * 16;
        float lg[8];
        float mx = -1e30f;
#pragma unroll
        for (int mm = 0; mm < 8; mm++) {
            int m = hf * 8 + mm;
            float s = b_sf2[m];
            const float4* w24 = (const float4*)(w_sf2 + m * 16);
#pragma unroll
            for (int i4 = 0; i4 < 4; i4++) {
                float4 w4 = w24[i4];
                s += w4.x * hv[4 * i4] + w4.y * hv[4 * i4 + 1]
                   + w4.z * hv[4 * i4 + 2] + w4.w * hv[4 * i4 + 3];
            }
            s += rp[m];
            lg[mm] = s;
            mx = fmaxf(mx, s);
        }
        mx = fmaxf(mx, __shfl_xor_sync(0xffffffffu, mx, 1));
        float den = 0.f;
#pragma unroll
        for (int mm = 0; mm < 8; mm++) { lg[mm] = __expf(lg[mm] - mx); den += lg[mm]; }
        den += __shfl_xor_sync(0xffffffffu, den, 1);
        const float inv = 1.0f / den;
        float wv_[16];
#pragma unroll
        for (int i = 0; i < 8; i++) {
            float mine  = lg[i] * inv;
            float other = __shfl_xor_sync(0xffffffffu, mine, 1);
            if (hf == 0) { wv_[i] = mine;  wv_[8 + i] = other; }
            else         { wv_[i] = other; wv_[8 + i] = mine;  }
        }
        float av[8];
        const float* vbase = S + VS + pi * 1152 + n * 288;
#pragma unroll
        for (int dd = 0; dd < 8; dd++) {
            int dv = hf * 8 + dd;
            const float2* vr = (const float2*)(vbase + dv * 18);
            float a = 0.f;
#pragma unroll
            for (int m2 = 0; m2 < 8; m2++) {
                float2 vv = vr[m2];
                a += wv_[2 * m2] * vv.x + wv_[2 * m2 + 1] * vv.y;
            }
            av[dd] = a;
        }
        float* ab = S + pi * PBS + 2048 + (n * 16 + p) * 16 + hf * 8;
        *(float4*)ab       = make_float4(av[0], av[1], av[2], av[3]);
        *(float4*)(ab + 4) = make_float4(av[4], av[5], av[6], av[7]);
    }
    __syncthreads();
    if (t < 128) {
        const int pi = t >> 6, tl = t & 63;
        const int plo = tl >> 4;
        const int dv  = tl & 15;
        const float* ab = S + pi * PBS + 2048;
        float s = 0.f;
#pragma unroll
        for (int n2 = 0; n2 < 4; n2++)
#pragma unroll
            for (int ph = 0; ph < 4; ph++)
                s += ab[(n2 * 16 + ph * 4 + plo) * 16 + dv];
        S[CS + pi * 64 + tl] = s;
    }
    __syncthreads();

    // ---------------- Phase 5: projection + sum ----------------
    if (t < 128) {
        const int pi = t >> 6, o = t & 63;
        const float* cs = S + CS + pi * 64;
        float acc = 16.0f * b_proj[o];
#pragma unroll 8
        for (int j = 0; j < 64; j++) acc += cs[j] * g_wpt[(j << 6) | o];
        out[b * 65536 + o * 1024 + oys[pi] * 32 + oxs[pi]] = acc;
    }
}

extern "C" void kernel_launch(void* const* d_in, const int* in_sizes, int n_in,
                              void* d_out, int out_size)
{
    (void)in_sizes; (void)n_in; (void)out_size;
    cudaFuncSetAttribute(selfattn2d_kernel,
                         cudaFuncAttributeMaxDynamicSharedMemorySize,
                         SMEM_FLOATS * sizeof(float));
    prep_kernel<<<64, 256>>>(
        (const float*)d_in[1],  // wq
        (const float*)d_in[2],  // wk
        (const float*)d_in[3],  // wv
        (const float*)d_in[4],  // w_rel
        (const float*)d_in[5],  // w_deconv
        (const float*)d_in[10]);// w_proj
    selfattn2d_kernel<<<2048, 256, SMEM_FLOATS * sizeof(float)>>>(
        (const float*)d_in[0],  // x
        (const float*)d_in[6],  // w_sf1
        (const float*)d_in[7],  // b_sf1
        (const float*)d_in[8],  // w_sf2
        (const float*)d_in[9],  // b_sf2
        (const float*)d_in[11], // b_proj
        (float*)d_out);
}